// round 5
// baseline (speedup 1.0000x reference)
#include <cuda_runtime.h>
#include <cuda_bf16.h>
#include <math.h>
#include <stdint.h>

// Problem constants
#define BATCH   2
#define TSEQ    2048
#define BT      4096          // BATCH*TSEQ
#define DM      512
#define NH      8
#define DH      64
#define DV      64
#define CHUNK   64
#define NCHUNK  (TSEQ / CHUNK)   // 32
#define NBH     (BATCH * NH)     // 16

// ---------------- scratch (device globals; no allocation allowed) ----------
__device__ float g_Q[BT * DM];
__device__ float g_K[BT * DM];
__device__ float g_V[BT * DM];
__device__ float g_KtV [NBH * NCHUNK * DH * DV];
__device__ float g_Spre[NBH * NCHUNK * DH * DV];
__device__ float g_ksum[NBH * NCHUNK * DH];
__device__ float g_zpre[NBH * NCHUNK * DH];

// bf16 hi/lo split operands for tensor-core GEMMs
__device__ __nv_bfloat16 g_xh[BT * DM],  g_xl[BT * DM];
__device__ __nv_bfloat16 g_Ah[BT * DM],  g_Al[BT * DM];     // attention output
__device__ __nv_bfloat16 g_Wqh[DM * DM], g_Wql[DM * DM];
__device__ __nv_bfloat16 g_Wkh[DM * DM], g_Wkl[DM * DM];
__device__ __nv_bfloat16 g_Wvh[DM * DM], g_Wvl[DM * DM];
__device__ __nv_bfloat16 g_Woh[DM * DM], g_Wol[DM * DM];

// ============================================================================
// Helpers
// ============================================================================
__device__ __forceinline__ uint32_t smem_u32(const void* p) {
    uint32_t a;
    asm("{ .reg .u64 t; cvta.to.shared.u64 t, %1; cvt.u32.u64 %0, t; }"
        : "=r"(a) : "l"(p));
    return a;
}

__device__ __forceinline__ uint32_t pack_bf2(__nv_bfloat16 a, __nv_bfloat16 b) {
    return (uint32_t)__bfloat16_as_ushort(a) |
           ((uint32_t)__bfloat16_as_ushort(b) << 16);
}

// phi(t) = elu(t) + 1
__device__ __forceinline__ float elu1(float t) {
    return (t > 0.f) ? (t + 1.f) : __expf(t);
}

// warp mma: D(16x8,f32) += A(16x16,bf16,row) * B(16x8,bf16,col)
__device__ __forceinline__ void mma16816(float d[4], const uint32_t a[4],
                                         const uint32_t b[2]) {
    asm("mma.sync.aligned.m16n8k16.row.col.f32.bf16.bf16.f32 "
        "{%0,%1,%2,%3}, {%4,%5,%6,%7}, {%8,%9}, {%0,%1,%2,%3};"
        : "+f"(d[0]), "+f"(d[1]), "+f"(d[2]), "+f"(d[3])
        : "r"(a[0]), "r"(a[1]), "r"(a[2]), "r"(a[3]), "r"(b[0]), "r"(b[1]));
}

__device__ __forceinline__ void ldmx4(uint32_t r[4], uint32_t addr) {
    asm volatile("ldmatrix.sync.aligned.m8n8.x4.shared.b16 {%0,%1,%2,%3}, [%4];"
                 : "=r"(r[0]), "=r"(r[1]), "=r"(r[2]), "=r"(r[3]) : "r"(addr));
}

__device__ __forceinline__ void cp16(uint32_t saddr, const void* g) {
    asm volatile("cp.async.cg.shared.global [%0], [%1], 16;"
                 :: "r"(saddr), "l"(g) : "memory");
}
#define CP_COMMIT() asm volatile("cp.async.commit_group;" ::: "memory")
#define CP_WAIT(n)  asm volatile("cp.async.wait_group %0;" :: "n"(n) : "memory")

// ---------------------------------------------------------------------------
// Kernel 0: fp32 -> bf16 hi + lo residual splits
// ---------------------------------------------------------------------------
__device__ __forceinline__ void split4(const float* __restrict__ src,
                                       __nv_bfloat16* __restrict__ dh,
                                       __nv_bfloat16* __restrict__ dl, int i)
{
    float4 f = *(const float4*)(src + i);
    __nv_bfloat16 h0 = __float2bfloat16_rn(f.x);
    __nv_bfloat16 h1 = __float2bfloat16_rn(f.y);
    __nv_bfloat16 h2 = __float2bfloat16_rn(f.z);
    __nv_bfloat16 h3 = __float2bfloat16_rn(f.w);
    __nv_bfloat16 l0 = __float2bfloat16_rn(f.x - __bfloat162float(h0));
    __nv_bfloat16 l1 = __float2bfloat16_rn(f.y - __bfloat162float(h1));
    __nv_bfloat16 l2 = __float2bfloat16_rn(f.z - __bfloat162float(h2));
    __nv_bfloat16 l3 = __float2bfloat16_rn(f.w - __bfloat162float(h3));
    *(uint2*)(dh + i) = make_uint2(pack_bf2(h0, h1), pack_bf2(h2, h3));
    *(uint2*)(dl + i) = make_uint2(pack_bf2(l0, l1), pack_bf2(l2, l3));
}

__global__ __launch_bounds__(256)
void split_x(const float* __restrict__ src)
{
    int i = (blockIdx.x * 256 + threadIdx.x) * 4;
    if (i < BT * DM) split4(src, g_xh, g_xl, i);
}

__global__ __launch_bounds__(256)
void split_w4(const float* __restrict__ w0, const float* __restrict__ w1,
              const float* __restrict__ w2, const float* __restrict__ w3)
{
    const int sel = blockIdx.y;
    const float* src = (sel == 0) ? w0 : (sel == 1) ? w1 : (sel == 2) ? w2 : w3;
    __nv_bfloat16* dh = (sel == 0) ? g_Wqh : (sel == 1) ? g_Wkh
                      : (sel == 2) ? g_Wvh : g_Woh;
    __nv_bfloat16* dl = (sel == 0) ? g_Wql : (sel == 1) ? g_Wkl
                      : (sel == 2) ? g_Wvl : g_Wol;
    int i = (blockIdx.x * 256 + threadIdx.x) * 4;
    if (i < DM * DM) split4(src, dh, dl, i);
}

// ============================================================================
// Tensor-core GEMM: C[m,n] = sum_k A[m,k]*B[n,k]  (fp32-via-3x-bf16)
// Block 128x128, BK=64, 8 warps (2m x 4n), warp tile 64x32.
// 2-stage cp.async pipeline; ldmatrix fragment loads; latency-ordered MMAs.
// ============================================================================
#define PITCH   72
#define TILE_E  (128 * PITCH)        // elems per tile
#define TILE_B  (TILE_E * 2)         // bytes per tile
#define STAGE_E (4 * TILE_E)
#define STAGE_B (4 * TILE_B)         // 73728 B
#define SMEM_GEMM_BYTES (2 * STAGE_B)  // 147456 B

__device__ __forceinline__ void tc_gemm_128x128(
    const __nv_bfloat16* __restrict__ Ahp, const __nv_bfloat16* __restrict__ Alp,
    const __nv_bfloat16* __restrict__ Bhp, const __nv_bfloat16* __restrict__ Blp,
    int m0, int n0, float* __restrict__ C, bool act)
{
    extern __shared__ __nv_bfloat16 sb[];
    const uint32_t smb = smem_u32(sb);

    const int tid  = threadIdx.x;
    const int w    = tid >> 5;
    const int lane = tid & 31;
    const int g    = lane >> 2;      // 0..7
    const int q    = lane & 3;       // 0..3
    const int wm   = (w >> 2) * 64;  // warp m offset
    const int wn   = (w & 3) * 32;   // warp n offset

    const int row = tid >> 1;        // 0..127 (staging)
    const int kh  = (tid & 1) * 32;  // 0 or 32
    const uint32_t sOff = (uint32_t)(row * PITCH + kh) * 2;

    // ldmatrix per-lane base addresses (within stage 0, tile 0)
    const int sel = lane >> 3;       // 0..3
    const int rr  = lane & 7;        // 0..7
    // A frag: matrices (rows 0-7 / 8-15) x (cols 0-7 / 8-15)
    const uint32_t aBase = smb +
        (uint32_t)(((wm + (sel & 1) * 8 + rr) * PITCH) + (sel >> 1) * 8) * 2;
    // B frag: matrices (ni pair row blocks) x (cols 0-7 / 8-15)
    const uint32_t bBase = smb + 2 * TILE_B +
        (uint32_t)(((wn + (sel >> 1) * 8 + rr) * PITCH) + (sel & 1) * 8) * 2;

    float acc[4][4][4];
    #pragma unroll
    for (int mi = 0; mi < 4; mi++)
        #pragma unroll
        for (int ni = 0; ni < 4; ni++)
            #pragma unroll
            for (int r = 0; r < 4; r++) acc[mi][ni][r] = 0.f;

    auto issue = [&](int c) {
        const uint32_t base = smb + (uint32_t)(c & 1) * STAGE_B;
        const __nv_bfloat16* gA  = Ahp + (size_t)(m0 + row) * DM + c * 64 + kh;
        const __nv_bfloat16* gAl = Alp + (size_t)(m0 + row) * DM + c * 64 + kh;
        const __nv_bfloat16* gB  = Bhp + (size_t)(n0 + row) * DM + c * 64 + kh;
        const __nv_bfloat16* gBl = Blp + (size_t)(n0 + row) * DM + c * 64 + kh;
        #pragma unroll
        for (int i = 0; i < 4; i++) {
            cp16(base + 0 * TILE_B + sOff + i * 16, gA  + i * 8);
            cp16(base + 1 * TILE_B + sOff + i * 16, gAl + i * 8);
            cp16(base + 2 * TILE_B + sOff + i * 16, gB  + i * 8);
            cp16(base + 3 * TILE_B + sOff + i * 16, gBl + i * 8);
        }
        CP_COMMIT();
    };

    issue(0);

    #pragma unroll 1
    for (int c = 0; c < 8; c++) {
        if (c < 7) {
            issue(c + 1);
            CP_WAIT(1);
        } else {
            CP_WAIT(0);
        }
        __syncthreads();

        const uint32_t stage = (uint32_t)(c & 1) * STAGE_B;

        #pragma unroll
        for (int kk = 0; kk < 4; kk++) {
            const uint32_t ko = (uint32_t)kk * 32;  // bytes along k
            uint32_t ah[4][4], al[4][4], bh[2][4], bl[2][4];
            #pragma unroll
            for (int mi = 0; mi < 4; mi++) {
                const uint32_t mo = (uint32_t)mi * 16 * PITCH * 2;
                ldmx4(ah[mi], aBase + stage + mo + ko);
                ldmx4(al[mi], aBase + stage + TILE_B + mo + ko);
            }
            #pragma unroll
            for (int nb = 0; nb < 2; nb++) {
                const uint32_t no = (uint32_t)nb * 16 * PITCH * 2;
                ldmx4(bh[nb], bBase + stage + no + ko);
                ldmx4(bl[nb], bBase + stage + TILE_B + no + ko);
            }
            // three passes of 16 independent accumulators each
            #pragma unroll
            for (int mi = 0; mi < 4; mi++)
                #pragma unroll
                for (int ni = 0; ni < 4; ni++)
                    mma16816(acc[mi][ni], ah[mi], &bh[ni >> 1][(ni & 1) * 2]);
            #pragma unroll
            for (int mi = 0; mi < 4; mi++)
                #pragma unroll
                for (int ni = 0; ni < 4; ni++)
                    mma16816(acc[mi][ni], ah[mi], &bl[ni >> 1][(ni & 1) * 2]);
            #pragma unroll
            for (int mi = 0; mi < 4; mi++)
                #pragma unroll
                for (int ni = 0; ni < 4; ni++)
                    mma16816(acc[mi][ni], al[mi], &bh[ni >> 1][(ni & 1) * 2]);
        }
        __syncthreads();
    }

    // epilogue: D fragment -> global (optional elu+1)
    #pragma unroll
    for (int mi = 0; mi < 4; mi++) {
        const int r0 = m0 + wm + mi * 16 + g;
        #pragma unroll
        for (int ni = 0; ni < 4; ni++) {
            const int col = n0 + wn + ni * 8 + q * 2;
            float2 v0 = make_float2(acc[mi][ni][0], acc[mi][ni][1]);
            float2 v1 = make_float2(acc[mi][ni][2], acc[mi][ni][3]);
            if (act) {
                v0.x = elu1(v0.x); v0.y = elu1(v0.y);
                v1.x = elu1(v1.x); v1.y = elu1(v1.y);
            }
            *(float2*)(C + (size_t)r0 * DM + col)       = v0;
            *(float2*)(C + (size_t)(r0 + 8) * DM + col) = v1;
        }
    }
}

// ---------------------------------------------------------------------------
// Kernel 1: fused QKV projection. grid = (BT/128, 12).
// ---------------------------------------------------------------------------
__global__ __launch_bounds__(256)
void gemm_qkv_tc()
{
    const int w  = blockIdx.y >> 2;
    const int n0 = (blockIdx.y & 3) * 128;
    const int m0 = blockIdx.x * 128;
    const __nv_bfloat16* Bh = (w == 0) ? g_Wqh : (w == 1) ? g_Wkh : g_Wvh;
    const __nv_bfloat16* Bl = (w == 0) ? g_Wql : (w == 1) ? g_Wkl : g_Wvl;
    float* Cp = (w == 0) ? g_Q : (w == 1) ? g_K : g_V;
    tc_gemm_128x128(g_xh, g_xl, Bh, Bl, m0, n0, Cp, w < 2);
}

// ---------------------------------------------------------------------------
// Kernel 5: output projection. grid = (BT/128, 4).
// ---------------------------------------------------------------------------
__global__ __launch_bounds__(256)
void gemm_out_tc(float* __restrict__ out)
{
    tc_gemm_128x128(g_Ah, g_Al, g_Woh, g_Wol,
                    blockIdx.x * 128, blockIdx.y * 128, out, false);
}

// ---------------------------------------------------------------------------
// Kernel 2: per-chunk K^T V and k-rowsum. grid = (NCHUNK, NBH), 256 threads.
// ---------------------------------------------------------------------------
__global__ __launch_bounds__(256)
void chunk_kv()
{
    const int c  = blockIdx.x;
    const int bh = blockIdx.y;
    const int b  = bh >> 3, h = bh & 7;
    const int tid = threadIdx.x;

    __shared__ float Ks[CHUNK * 68];
    __shared__ float Vs[CHUNK * 68];

    #pragma unroll
    for (int it = 0; it < 4; it++) {
        int idx  = tid + it * 256;        // 0..1023
        int row  = idx >> 4;              // tau
        int c4   = idx & 15;
        int go   = (b * TSEQ + c * CHUNK + row) * DM + h * DH + c4 * 4;
        *(float4*)&Ks[row * 68 + c4 * 4] = *(const float4*)&g_K[go];
        *(float4*)&Vs[row * 68 + c4 * 4] = *(const float4*)&g_V[go];
    }
    __syncthreads();

    const int ti = (tid & 15) * 4;   // i tile
    const int tj = (tid >> 4) * 4;   // j tile
    float acc[4][4] = {};
    #pragma unroll 4
    for (int t = 0; t < CHUNK; t++) {
        float4 kv = *(const float4*)&Ks[t * 68 + ti];
        float4 vv = *(const float4*)&Vs[t * 68 + tj];
        float kk[4] = {kv.x, kv.y, kv.z, kv.w};
        float vvv[4] = {vv.x, vv.y, vv.z, vv.w};
        #pragma unroll
        for (int a = 0; a < 4; a++)
            #pragma unroll
            for (int bb = 0; bb < 4; bb++)
                acc[a][bb] = fmaf(kk[a], vvv[bb], acc[a][bb]);
    }

    float* dst = g_KtV + (bh * NCHUNK + c) * (DH * DV);
    #pragma unroll
    for (int a = 0; a < 4; a++)
        *(float4*)&dst[(ti + a) * DV + tj] =
            make_float4(acc[a][0], acc[a][1], acc[a][2], acc[a][3]);

    if (tid < DH) {
        float s = 0.f;
        #pragma unroll 8
        for (int t = 0; t < CHUNK; t++) s += Ks[t * 68 + tid];
        g_ksum[(bh * NCHUNK + c) * DH + tid] = s;
    }
}

// ---------------------------------------------------------------------------
// Kernel 3: exclusive prefix-sum of chunk states over the chunk axis.
// ---------------------------------------------------------------------------
__global__ __launch_bounds__(256)
void prefix_state()
{
    const int bh  = blockIdx.x;
    const int tid = threadIdx.x;
    const float* src = g_KtV  + bh * NCHUNK * DH * DV;
    float*       dst = g_Spre + bh * NCHUNK * DH * DV;

    for (int g = 0; g < (DH * DV) / 256; g++) {
        int e = g * 256 + tid;
        float acc = 0.f;
        for (int c = 0; c < NCHUNK; c++) {
            dst[c * (DH * DV) + e] = acc;
            acc += src[c * (DH * DV) + e];
        }
    }
    if (tid < DH) {
        float acc = 0.f;
        for (int c = 0; c < NCHUNK; c++) {
            g_zpre[(bh * NCHUNK + c) * DH + tid] = acc;
            acc += g_ksum[(bh * NCHUNK + c) * DH + tid];
        }
    }
}

// ---------------------------------------------------------------------------
// Kernel 4: per-chunk attention. grid = (NCHUNK, NBH), 256 threads.
// Epilogue writes bf16 hi/lo split directly (consumed by gemm_out_tc).
// ---------------------------------------------------------------------------
#define SMEM_B_BYTES ((5 * 64 * 68 + 128) * 4)

__global__ __launch_bounds__(256)
void attn_chunk()
{
    extern __shared__ float smf[];
    float* Qt = smf;                // [i][tau]  transposed, stride 68
    float* Kt = Qt + 64 * 68;       // [i][sigma] transposed
    float* Vs = Kt + 64 * 68;       // [sigma][j]
    float* Ss = Vs + 64 * 68;       // [i][j]
    float* At = Ss + 64 * 68;       // [sigma][tau] (A transposed, masked)
    float* zp = At + 64 * 68;       // [64]
    float* dn = zp + 64;            // [64]

    const int c  = blockIdx.x;
    const int bh = blockIdx.y;
    const int b  = bh >> 3, h = bh & 7;
    const int tid = threadIdx.x;

    const float* sp = g_Spre + (bh * NCHUNK + c) * (DH * DV);

    #pragma unroll
    for (int it = 0; it < 4; it++) {
        int idx = tid + it * 256;
        int row = idx >> 4;
        int c4  = idx & 15;
        int go  = (b * TSEQ + c * CHUNK + row) * DM + h * DH + c4 * 4;
        float4 q = *(const float4*)&g_Q[go];
        float4 k = *(const float4*)&g_K[go];
        float4 v = *(const float4*)&g_V[go];
        Qt[(c4 * 4 + 0) * 68 + row] = q.x;
        Qt[(c4 * 4 + 1) * 68 + row] = q.y;
        Qt[(c4 * 4 + 2) * 68 + row] = q.z;
        Qt[(c4 * 4 + 3) * 68 + row] = q.w;
        Kt[(c4 * 4 + 0) * 68 + row] = k.x;
        Kt[(c4 * 4 + 1) * 68 + row] = k.y;
        Kt[(c4 * 4 + 2) * 68 + row] = k.z;
        Kt[(c4 * 4 + 3) * 68 + row] = k.w;
        *(float4*)&Vs[row * 68 + c4 * 4] = v;
        *(float4*)&Ss[row * 68 + c4 * 4] = *(const float4*)&sp[idx * 4];
    }
    if (tid < 16)
        *(float4*)&zp[tid * 4] =
            *(const float4*)&g_zpre[(bh * NCHUNK + c) * DH + tid * 4];
    __syncthreads();

    const int tt = (tid & 15) * 4;   // tau tile
    const int tj = (tid >> 4) * 4;   // j / sigma tile

    float o[4][4] = {};
    float aa[4][4] = {};

    #pragma unroll 4
    for (int i = 0; i < 64; i++) {
        float4 qa = *(const float4*)&Qt[i * 68 + tt];
        float4 sb = *(const float4*)&Ss[i * 68 + tj];
        float4 kb = *(const float4*)&Kt[i * 68 + tj];
        float q[4] = {qa.x, qa.y, qa.z, qa.w};
        float s[4] = {sb.x, sb.y, sb.z, sb.w};
        float k[4] = {kb.x, kb.y, kb.z, kb.w};
        #pragma unroll
        for (int a = 0; a < 4; a++)
            #pragma unroll
            for (int bb = 0; bb < 4; bb++) {
                o[a][bb]  = fmaf(q[a], s[bb], o[a][bb]);
                aa[a][bb] = fmaf(q[a], k[bb], aa[a][bb]);
            }
    }

    #pragma unroll
    for (int bb = 0; bb < 4; bb++) {
        int sig = tj + bb;
        float4 col;
        col.x = (sig <= tt + 0) ? aa[0][bb] : 0.f;
        col.y = (sig <= tt + 1) ? aa[1][bb] : 0.f;
        col.z = (sig <= tt + 2) ? aa[2][bb] : 0.f;
        col.w = (sig <= tt + 3) ? aa[3][bb] : 0.f;
        *(float4*)&At[sig * 68 + tt] = col;
    }
    __syncthreads();

    if (tid < 64) {
        float d = 0.f;
        #pragma unroll 8
        for (int i = 0; i < 64; i++) d = fmaf(Qt[i * 68 + tid], zp[i], d);
        #pragma unroll 8
        for (int s = 0; s < 64; s++) d += At[s * 68 + tid];
        dn[tid] = fmaxf(d, 1e-6f);
    }

    #pragma unroll 4
    for (int s = 0; s < 64; s++) {
        float4 av = *(const float4*)&At[s * 68 + tt];
        float4 vv = *(const float4*)&Vs[s * 68 + tj];
        float a4[4] = {av.x, av.y, av.z, av.w};
        float v4[4] = {vv.x, vv.y, vv.z, vv.w};
        #pragma unroll
        for (int a = 0; a < 4; a++)
            #pragma unroll
            for (int bb = 0; bb < 4; bb++)
                o[a][bb] = fmaf(a4[a], v4[bb], o[a][bb]);
    }
    __syncthreads();

    #pragma unroll
    for (int a = 0; a < 4; a++) {
        float r = 1.f / dn[tt + a];
        int go = (b * TSEQ + c * CHUNK + tt + a) * DM + h * DV + tj;
        float v0 = o[a][0] * r, v1 = o[a][1] * r;
        float v2 = o[a][2] * r, v3 = o[a][3] * r;
        __nv_bfloat16 h0 = __float2bfloat16_rn(v0);
        __nv_bfloat16 h1 = __float2bfloat16_rn(v1);
        __nv_bfloat16 h2 = __float2bfloat16_rn(v2);
        __nv_bfloat16 h3 = __float2bfloat16_rn(v3);
        __nv_bfloat16 l0 = __float2bfloat16_rn(v0 - __bfloat162float(h0));
        __nv_bfloat16 l1 = __float2bfloat16_rn(v1 - __bfloat162float(h1));
        __nv_bfloat16 l2 = __float2bfloat16_rn(v2 - __bfloat162float(h2));
        __nv_bfloat16 l3 = __float2bfloat16_rn(v3 - __bfloat162float(h3));
        *(uint2*)&g_Ah[go] = make_uint2(pack_bf2(h0, h1), pack_bf2(h2, h3));
        *(uint2*)&g_Al[go] = make_uint2(pack_bf2(l0, l1), pack_bf2(l2, l3));
    }
}

// ---------------------------------------------------------------------------
extern "C" void kernel_launch(void* const* d_in, const int* in_sizes, int n_in,
                              void* d_out, int out_size)
{
    const float* x    = (const float*)d_in[0];
    const float* Wq   = (const float*)d_in[1];
    const float* Wk   = (const float*)d_in[2];
    const float* Wv   = (const float*)d_in[3];
    const float* Wout = (const float*)d_in[4];
    float* out = (float*)d_out;

    cudaFuncSetAttribute(attn_chunk,
                         cudaFuncAttributeMaxDynamicSharedMemorySize,
                         SMEM_B_BYTES);
    cudaFuncSetAttribute(gemm_qkv_tc,
                         cudaFuncAttributeMaxDynamicSharedMemorySize,
                         SMEM_GEMM_BYTES);
    cudaFuncSetAttribute(gemm_out_tc,
                         cudaFuncAttributeMaxDynamicSharedMemorySize,
                         SMEM_GEMM_BYTES);

    split_x <<<BT * DM / 1024, 256>>>(x);
    split_w4<<<dim3(DM * DM / 1024, 4), 256>>>(Wq, Wk, Wv, Wout);

    gemm_qkv_tc <<<dim3(BT / 128, 12), 256, SMEM_GEMM_BYTES>>>();
    chunk_kv    <<<dim3(NCHUNK, NBH), 256>>>();
    prefix_state<<<NBH, 256>>>();
    attn_chunk  <<<dim3(NCHUNK, NBH), 256, SMEM_B_BYTES>>>();
    gemm_out_tc <<<dim3(BT / 128, 4), 256, SMEM_GEMM_BYTES>>>(out);
}

// round 6
// speedup vs baseline: 1.7665x; 1.7665x over previous
#include <cuda_runtime.h>
#include <cuda_bf16.h>
#include <math.h>
#include <stdint.h>

// Problem constants
#define BATCH   2
#define TSEQ    2048
#define BT      4096          // BATCH*TSEQ
#define DM      512
#define NH      8
#define DH      64
#define DV      64
#define CHUNK   64
#define NCHUNK  (TSEQ / CHUNK)   // 32
#define NBH     (BATCH * NH)     // 16

// ---------------- scratch (device globals; no allocation allowed) ----------
__device__ float g_Q[BT * DM];
__device__ float g_K[BT * DM];
__device__ float g_V[BT * DM];
__device__ float g_KtV [NBH * NCHUNK * DH * DV];
__device__ float g_Spre[NBH * NCHUNK * DH * DV];
__device__ float g_ksum[NBH * NCHUNK * DH];
__device__ float g_zpre[NBH * NCHUNK * DH];

// bf16 hi/lo split operands for tensor-core GEMMs
__device__ __nv_bfloat16 g_xh[BT * DM],  g_xl[BT * DM];
__device__ __nv_bfloat16 g_Ah[BT * DM],  g_Al[BT * DM];     // attention output
__device__ __nv_bfloat16 g_Wqh[DM * DM], g_Wql[DM * DM];
__device__ __nv_bfloat16 g_Wkh[DM * DM], g_Wkl[DM * DM];
__device__ __nv_bfloat16 g_Wvh[DM * DM], g_Wvl[DM * DM];
__device__ __nv_bfloat16 g_Woh[DM * DM], g_Wol[DM * DM];

// ============================================================================
// Helpers
// ============================================================================
__device__ __forceinline__ uint32_t smem_u32(const void* p) {
    uint32_t a;
    asm("{ .reg .u64 t; cvta.to.shared.u64 t, %1; cvt.u32.u64 %0, t; }"
        : "=r"(a) : "l"(p));
    return a;
}

__device__ __forceinline__ uint32_t pack_bf2(__nv_bfloat16 a, __nv_bfloat16 b) {
    return (uint32_t)__bfloat16_as_ushort(a) |
           ((uint32_t)__bfloat16_as_ushort(b) << 16);
}

// phi(t) = elu(t) + 1
__device__ __forceinline__ float elu1(float t) {
    return (t > 0.f) ? (t + 1.f) : __expf(t);
}

// warp mma: D(16x8,f32) += A(16x16,bf16,row) * B(16x8,bf16,col)
__device__ __forceinline__ void mma16816(float d[4], const uint32_t a[4],
                                         const uint32_t b[2]) {
    asm("mma.sync.aligned.m16n8k16.row.col.f32.bf16.bf16.f32 "
        "{%0,%1,%2,%3}, {%4,%5,%6,%7}, {%8,%9}, {%0,%1,%2,%3};"
        : "+f"(d[0]), "+f"(d[1]), "+f"(d[2]), "+f"(d[3])
        : "r"(a[0]), "r"(a[1]), "r"(a[2]), "r"(a[3]), "r"(b[0]), "r"(b[1]));
}

__device__ __forceinline__ void ldmx4(uint32_t r[4], uint32_t addr) {
    asm volatile("ldmatrix.sync.aligned.m8n8.x4.shared.b16 {%0,%1,%2,%3}, [%4];"
                 : "=r"(r[0]), "=r"(r[1]), "=r"(r[2]), "=r"(r[3]) : "r"(addr));
}

__device__ __forceinline__ void cp16(uint32_t saddr, const void* g) {
    asm volatile("cp.async.cg.shared.global [%0], [%1], 16;"
                 :: "r"(saddr), "l"(g) : "memory");
}
#define CP_COMMIT() asm volatile("cp.async.commit_group;" ::: "memory")
#define CP_WAIT(n)  asm volatile("cp.async.wait_group %0;" :: "n"(n) : "memory")

// ---------------------------------------------------------------------------
// Kernel 0: fp32 -> bf16 hi + lo residual splits
// ---------------------------------------------------------------------------
__device__ __forceinline__ void split4(const float* __restrict__ src,
                                       __nv_bfloat16* __restrict__ dh,
                                       __nv_bfloat16* __restrict__ dl, int i)
{
    float4 f = *(const float4*)(src + i);
    __nv_bfloat16 h0 = __float2bfloat16_rn(f.x);
    __nv_bfloat16 h1 = __float2bfloat16_rn(f.y);
    __nv_bfloat16 h2 = __float2bfloat16_rn(f.z);
    __nv_bfloat16 h3 = __float2bfloat16_rn(f.w);
    __nv_bfloat16 l0 = __float2bfloat16_rn(f.x - __bfloat162float(h0));
    __nv_bfloat16 l1 = __float2bfloat16_rn(f.y - __bfloat162float(h1));
    __nv_bfloat16 l2 = __float2bfloat16_rn(f.z - __bfloat162float(h2));
    __nv_bfloat16 l3 = __float2bfloat16_rn(f.w - __bfloat162float(h3));
    *(uint2*)(dh + i) = make_uint2(pack_bf2(h0, h1), pack_bf2(h2, h3));
    *(uint2*)(dl + i) = make_uint2(pack_bf2(l0, l1), pack_bf2(l2, l3));
}

__global__ __launch_bounds__(256)
void split_x(const float* __restrict__ src)
{
    int i = (blockIdx.x * 256 + threadIdx.x) * 4;
    if (i < BT * DM) split4(src, g_xh, g_xl, i);
}

__global__ __launch_bounds__(256)
void split_w4(const float* __restrict__ w0, const float* __restrict__ w1,
              const float* __restrict__ w2, const float* __restrict__ w3)
{
    const int sel = blockIdx.y;
    const float* src = (sel == 0) ? w0 : (sel == 1) ? w1 : (sel == 2) ? w2 : w3;
    __nv_bfloat16* dh = (sel == 0) ? g_Wqh : (sel == 1) ? g_Wkh
                      : (sel == 2) ? g_Wvh : g_Woh;
    __nv_bfloat16* dl = (sel == 0) ? g_Wql : (sel == 1) ? g_Wkl
                      : (sel == 2) ? g_Wvl : g_Wol;
    int i = (blockIdx.x * 256 + threadIdx.x) * 4;
    if (i < DM * DM) split4(src, dh, dl, i);
}

// no-op kernel: keeps gemm_qkv_tc at launch index 3 so ncu (-s 5 -c 1,
// observed to capture launch idx 3) profiles the GEMM next round.
__global__ void nop_k() {}

// ============================================================================
// Tensor-core GEMM: C[m,n] = sum_k A[m,k]*B[n,k]  (fp32-via-3x-bf16)
// Block 128x128, BK=64, 8 warps (2m x 4n), warp tile 64x32.
// 2-stage cp.async pipeline; ldmatrix fragment loads; latency-ordered MMAs.
// ============================================================================
#define PITCH   72
#define TILE_E  (128 * PITCH)        // elems per tile
#define TILE_B  (TILE_E * 2)         // bytes per tile
#define STAGE_E (4 * TILE_E)
#define STAGE_B (4 * TILE_B)         // 73728 B
#define SMEM_GEMM_BYTES (2 * STAGE_B)  // 147456 B

__device__ __forceinline__ void tc_gemm_128x128(
    const __nv_bfloat16* __restrict__ Ahp, const __nv_bfloat16* __restrict__ Alp,
    const __nv_bfloat16* __restrict__ Bhp, const __nv_bfloat16* __restrict__ Blp,
    int m0, int n0, float* __restrict__ C, bool act)
{
    extern __shared__ __nv_bfloat16 sb[];
    const uint32_t smb = smem_u32(sb);

    const int tid  = threadIdx.x;
    const int w    = tid >> 5;
    const int lane = tid & 31;
    const int g    = lane >> 2;      // 0..7
    const int q    = lane & 3;       // 0..3
    const int wm   = (w >> 2) * 64;  // warp m offset
    const int wn   = (w & 3) * 32;   // warp n offset

    const int row = tid >> 1;        // 0..127 (staging)
    const int kh  = (tid & 1) * 32;  // 0 or 32
    const uint32_t sOff = (uint32_t)(row * PITCH + kh) * 2;

    // ldmatrix per-lane base addresses (within stage 0, tile 0)
    const int sel = lane >> 3;       // 0..3
    const int rr  = lane & 7;        // 0..7
    const uint32_t aBase = smb +
        (uint32_t)(((wm + (sel & 1) * 8 + rr) * PITCH) + (sel >> 1) * 8) * 2;
    const uint32_t bBase = smb + 2 * TILE_B +
        (uint32_t)(((wn + (sel >> 1) * 8 + rr) * PITCH) + (sel & 1) * 8) * 2;

    float acc[4][4][4];
    #pragma unroll
    for (int mi = 0; mi < 4; mi++)
        #pragma unroll
        for (int ni = 0; ni < 4; ni++)
            #pragma unroll
            for (int r = 0; r < 4; r++) acc[mi][ni][r] = 0.f;

    auto issue = [&](int c) {
        const uint32_t base = smb + (uint32_t)(c & 1) * STAGE_B;
        const __nv_bfloat16* gA  = Ahp + (size_t)(m0 + row) * DM + c * 64 + kh;
        const __nv_bfloat16* gAl = Alp + (size_t)(m0 + row) * DM + c * 64 + kh;
        const __nv_bfloat16* gB  = Bhp + (size_t)(n0 + row) * DM + c * 64 + kh;
        const __nv_bfloat16* gBl = Blp + (size_t)(n0 + row) * DM + c * 64 + kh;
        #pragma unroll
        for (int i = 0; i < 4; i++) {
            cp16(base + 0 * TILE_B + sOff + i * 16, gA  + i * 8);
            cp16(base + 1 * TILE_B + sOff + i * 16, gAl + i * 8);
            cp16(base + 2 * TILE_B + sOff + i * 16, gB  + i * 8);
            cp16(base + 3 * TILE_B + sOff + i * 16, gBl + i * 8);
        }
        CP_COMMIT();
    };

    issue(0);

    #pragma unroll 1
    for (int c = 0; c < 8; c++) {
        if (c < 7) {
            issue(c + 1);
            CP_WAIT(1);
        } else {
            CP_WAIT(0);
        }
        __syncthreads();

        const uint32_t stage = (uint32_t)(c & 1) * STAGE_B;

        #pragma unroll
        for (int kk = 0; kk < 4; kk++) {
            const uint32_t ko = (uint32_t)kk * 32;  // bytes along k
            uint32_t ah[4][4], al[4][4], bh[2][4], bl[2][4];
            #pragma unroll
            for (int mi = 0; mi < 4; mi++) {
                const uint32_t mo = (uint32_t)mi * 16 * PITCH * 2;
                ldmx4(ah[mi], aBase + stage + mo + ko);
                ldmx4(al[mi], aBase + stage + TILE_B + mo + ko);
            }
            #pragma unroll
            for (int nb = 0; nb < 2; nb++) {
                const uint32_t no = (uint32_t)nb * 16 * PITCH * 2;
                ldmx4(bh[nb], bBase + stage + no + ko);
                ldmx4(bl[nb], bBase + stage + TILE_B + no + ko);
            }
            #pragma unroll
            for (int mi = 0; mi < 4; mi++)
                #pragma unroll
                for (int ni = 0; ni < 4; ni++)
                    mma16816(acc[mi][ni], ah[mi], &bh[ni >> 1][(ni & 1) * 2]);
            #pragma unroll
            for (int mi = 0; mi < 4; mi++)
                #pragma unroll
                for (int ni = 0; ni < 4; ni++)
                    mma16816(acc[mi][ni], ah[mi], &bl[ni >> 1][(ni & 1) * 2]);
            #pragma unroll
            for (int mi = 0; mi < 4; mi++)
                #pragma unroll
                for (int ni = 0; ni < 4; ni++)
                    mma16816(acc[mi][ni], al[mi], &bh[ni >> 1][(ni & 1) * 2]);
        }
        __syncthreads();
    }

    // epilogue: D fragment -> global (optional elu+1)
    #pragma unroll
    for (int mi = 0; mi < 4; mi++) {
        const int r0 = m0 + wm + mi * 16 + g;
        #pragma unroll
        for (int ni = 0; ni < 4; ni++) {
            const int col = n0 + wn + ni * 8 + q * 2;
            float2 v0 = make_float2(acc[mi][ni][0], acc[mi][ni][1]);
            float2 v1 = make_float2(acc[mi][ni][2], acc[mi][ni][3]);
            if (act) {
                v0.x = elu1(v0.x); v0.y = elu1(v0.y);
                v1.x = elu1(v1.x); v1.y = elu1(v1.y);
            }
            *(float2*)(C + (size_t)r0 * DM + col)       = v0;
            *(float2*)(C + (size_t)(r0 + 8) * DM + col) = v1;
        }
    }
}

// ---------------------------------------------------------------------------
// Kernel 1: fused QKV projection. grid = (BT/128, 12).
// ---------------------------------------------------------------------------
__global__ __launch_bounds__(256, 1)
void gemm_qkv_tc()
{
    const int w  = blockIdx.y >> 2;
    const int n0 = (blockIdx.y & 3) * 128;
    const int m0 = blockIdx.x * 128;
    const __nv_bfloat16* Bh = (w == 0) ? g_Wqh : (w == 1) ? g_Wkh : g_Wvh;
    const __nv_bfloat16* Bl = (w == 0) ? g_Wql : (w == 1) ? g_Wkl : g_Wvl;
    float* Cp = (w == 0) ? g_Q : (w == 1) ? g_K : g_V;
    tc_gemm_128x128(g_xh, g_xl, Bh, Bl, m0, n0, Cp, w < 2);
}

// ---------------------------------------------------------------------------
// Kernel 5: output projection. grid = (BT/128, 4).
// ---------------------------------------------------------------------------
__global__ __launch_bounds__(256, 1)
void gemm_out_tc(float* __restrict__ out)
{
    tc_gemm_128x128(g_Ah, g_Al, g_Woh, g_Wol,
                    blockIdx.x * 128, blockIdx.y * 128, out, false);
}

// ---------------------------------------------------------------------------
// Kernel 2: per-chunk K^T V and k-rowsum. grid = (NCHUNK, NBH), 256 threads.
// ---------------------------------------------------------------------------
__global__ __launch_bounds__(256)
void chunk_kv()
{
    const int c  = blockIdx.x;
    const int bh = blockIdx.y;
    const int b  = bh >> 3, h = bh & 7;
    const int tid = threadIdx.x;

    __shared__ float Ks[CHUNK * 68];
    __shared__ float Vs[CHUNK * 68];

    #pragma unroll
    for (int it = 0; it < 4; it++) {
        int idx  = tid + it * 256;        // 0..1023
        int row  = idx >> 4;              // tau
        int c4   = idx & 15;
        int go   = (b * TSEQ + c * CHUNK + row) * DM + h * DH + c4 * 4;
        *(float4*)&Ks[row * 68 + c4 * 4] = *(const float4*)&g_K[go];
        *(float4*)&Vs[row * 68 + c4 * 4] = *(const float4*)&g_V[go];
    }
    __syncthreads();

    const int ti = (tid & 15) * 4;   // i tile
    const int tj = (tid >> 4) * 4;   // j tile
    float acc[4][4] = {};
    #pragma unroll 4
    for (int t = 0; t < CHUNK; t++) {
        float4 kv = *(const float4*)&Ks[t * 68 + ti];
        float4 vv = *(const float4*)&Vs[t * 68 + tj];
        float kk[4] = {kv.x, kv.y, kv.z, kv.w};
        float vvv[4] = {vv.x, vv.y, vv.z, vv.w};
        #pragma unroll
        for (int a = 0; a < 4; a++)
            #pragma unroll
            for (int bb = 0; bb < 4; bb++)
                acc[a][bb] = fmaf(kk[a], vvv[bb], acc[a][bb]);
    }

    float* dst = g_KtV + (bh * NCHUNK + c) * (DH * DV);
    #pragma unroll
    for (int a = 0; a < 4; a++)
        *(float4*)&dst[(ti + a) * DV + tj] =
            make_float4(acc[a][0], acc[a][1], acc[a][2], acc[a][3]);

    if (tid < DH) {
        float s = 0.f;
        #pragma unroll 8
        for (int t = 0; t < CHUNK; t++) s += Ks[t * 68 + tid];
        g_ksum[(bh * NCHUNK + c) * DH + tid] = s;
    }
}

// ---------------------------------------------------------------------------
// Kernel 3: exclusive prefix-sum over chunks — fully parallel.
// grid = (16, NBH), 256 threads; each thread scans ONE state element
// across all 32 chunks (independent unrolled loads -> MLP=32, coalesced).
// ---------------------------------------------------------------------------
__global__ __launch_bounds__(256)
void prefix_state2()
{
    const int bh = blockIdx.y;
    const int e  = blockIdx.x * 256 + threadIdx.x;
    const float* src = g_KtV  + (size_t)bh * NCHUNK * (DH * DV) + e;
    float*       dst = g_Spre + (size_t)bh * NCHUNK * (DH * DV) + e;

    float v[NCHUNK];
    #pragma unroll
    for (int c = 0; c < NCHUNK; c++) v[c] = src[c * (DH * DV)];
    float acc = 0.f;
    #pragma unroll
    for (int c = 0; c < NCHUNK; c++) {
        dst[c * (DH * DV)] = acc;
        acc += v[c];
    }

    if (blockIdx.x == 0 && threadIdx.x < DH) {
        const float* ks = g_ksum + bh * NCHUNK * DH + threadIdx.x;
        float wz[NCHUNK];
        #pragma unroll
        for (int c = 0; c < NCHUNK; c++) wz[c] = ks[c * DH];
        float a = 0.f;
        #pragma unroll
        for (int c = 0; c < NCHUNK; c++) {
            g_zpre[bh * NCHUNK * DH + c * DH + threadIdx.x] = a;
            a += wz[c];
        }
    }
}

// ---------------------------------------------------------------------------
// Kernel 4: per-chunk attention. grid = (NCHUNK, NBH), 256 threads.
// Epilogue writes bf16 hi/lo split directly (consumed by gemm_out_tc).
// ---------------------------------------------------------------------------
#define SMEM_B_BYTES ((5 * 64 * 68 + 128) * 4)

__global__ __launch_bounds__(256)
void attn_chunk()
{
    extern __shared__ float smf[];
    float* Qt = smf;                // [i][tau]  transposed, stride 68
    float* Kt = Qt + 64 * 68;       // [i][sigma] transposed
    float* Vs = Kt + 64 * 68;       // [sigma][j]
    float* Ss = Vs + 64 * 68;       // [i][j]
    float* At = Ss + 64 * 68;       // [sigma][tau] (A transposed, masked)
    float* zp = At + 64 * 68;       // [64]
    float* dn = zp + 64;            // [64]

    const int c  = blockIdx.x;
    const int bh = blockIdx.y;
    const int b  = bh >> 3, h = bh & 7;
    const int tid = threadIdx.x;

    const float* sp = g_Spre + (bh * NCHUNK + c) * (DH * DV);

    #pragma unroll
    for (int it = 0; it < 4; it++) {
        int idx = tid + it * 256;
        int row = idx >> 4;
        int c4  = idx & 15;
        int go  = (b * TSEQ + c * CHUNK + row) * DM + h * DH + c4 * 4;
        float4 q = *(const float4*)&g_Q[go];
        float4 k = *(const float4*)&g_K[go];
        float4 v = *(const float4*)&g_V[go];
        Qt[(c4 * 4 + 0) * 68 + row] = q.x;
        Qt[(c4 * 4 + 1) * 68 + row] = q.y;
        Qt[(c4 * 4 + 2) * 68 + row] = q.z;
        Qt[(c4 * 4 + 3) * 68 + row] = q.w;
        Kt[(c4 * 4 + 0) * 68 + row] = k.x;
        Kt[(c4 * 4 + 1) * 68 + row] = k.y;
        Kt[(c4 * 4 + 2) * 68 + row] = k.z;
        Kt[(c4 * 4 + 3) * 68 + row] = k.w;
        *(float4*)&Vs[row * 68 + c4 * 4] = v;
        *(float4*)&Ss[row * 68 + c4 * 4] = *(const float4*)&sp[idx * 4];
    }
    if (tid < 16)
        *(float4*)&zp[tid * 4] =
            *(const float4*)&g_zpre[(bh * NCHUNK + c) * DH + tid * 4];
    __syncthreads();

    const int tt = (tid & 15) * 4;   // tau tile
    const int tj = (tid >> 4) * 4;   // j / sigma tile

    float o[4][4] = {};
    float aa[4][4] = {};

    #pragma unroll 4
    for (int i = 0; i < 64; i++) {
        float4 qa = *(const float4*)&Qt[i * 68 + tt];
        float4 sb = *(const float4*)&Ss[i * 68 + tj];
        float4 kb = *(const float4*)&Kt[i * 68 + tj];
        float q[4] = {qa.x, qa.y, qa.z, qa.w};
        float s[4] = {sb.x, sb.y, sb.z, sb.w};
        float k[4] = {kb.x, kb.y, kb.z, kb.w};
        #pragma unroll
        for (int a = 0; a < 4; a++)
            #pragma unroll
            for (int bb = 0; bb < 4; bb++) {
                o[a][bb]  = fmaf(q[a], s[bb], o[a][bb]);
                aa[a][bb] = fmaf(q[a], k[bb], aa[a][bb]);
            }
    }

    #pragma unroll
    for (int bb = 0; bb < 4; bb++) {
        int sig = tj + bb;
        float4 col;
        col.x = (sig <= tt + 0) ? aa[0][bb] : 0.f;
        col.y = (sig <= tt + 1) ? aa[1][bb] : 0.f;
        col.z = (sig <= tt + 2) ? aa[2][bb] : 0.f;
        col.w = (sig <= tt + 3) ? aa[3][bb] : 0.f;
        *(float4*)&At[sig * 68 + tt] = col;
    }
    __syncthreads();

    if (tid < 64) {
        float d = 0.f;
        #pragma unroll 8
        for (int i = 0; i < 64; i++) d = fmaf(Qt[i * 68 + tid], zp[i], d);
        #pragma unroll 8
        for (int s = 0; s < 64; s++) d += At[s * 68 + tid];
        dn[tid] = fmaxf(d, 1e-6f);
    }

    #pragma unroll 4
    for (int s = 0; s < 64; s++) {
        float4 av = *(const float4*)&At[s * 68 + tt];
        float4 vv = *(const float4*)&Vs[s * 68 + tj];
        float a4[4] = {av.x, av.y, av.z, av.w};
        float v4[4] = {vv.x, vv.y, vv.z, vv.w};
        #pragma unroll
        for (int a = 0; a < 4; a++)
            #pragma unroll
            for (int bb = 0; bb < 4; bb++)
                o[a][bb] = fmaf(a4[a], v4[bb], o[a][bb]);
    }
    __syncthreads();

    #pragma unroll
    for (int a = 0; a < 4; a++) {
        float r = 1.f / dn[tt + a];
        int go = (b * TSEQ + c * CHUNK + tt + a) * DM + h * DV + tj;
        float v0 = o[a][0] * r, v1 = o[a][1] * r;
        float v2 = o[a][2] * r, v3 = o[a][3] * r;
        __nv_bfloat16 h0 = __float2bfloat16_rn(v0);
        __nv_bfloat16 h1 = __float2bfloat16_rn(v1);
        __nv_bfloat16 h2 = __float2bfloat16_rn(v2);
        __nv_bfloat16 h3 = __float2bfloat16_rn(v3);
        __nv_bfloat16 l0 = __float2bfloat16_rn(v0 - __bfloat162float(h0));
        __nv_bfloat16 l1 = __float2bfloat16_rn(v1 - __bfloat162float(h1));
        __nv_bfloat16 l2 = __float2bfloat16_rn(v2 - __bfloat162float(h2));
        __nv_bfloat16 l3 = __float2bfloat16_rn(v3 - __bfloat162float(h3));
        *(uint2*)&g_Ah[go] = make_uint2(pack_bf2(h0, h1), pack_bf2(h2, h3));
        *(uint2*)&g_Al[go] = make_uint2(pack_bf2(l0, l1), pack_bf2(l2, l3));
    }
}

// ---------------------------------------------------------------------------
extern "C" void kernel_launch(void* const* d_in, const int* in_sizes, int n_in,
                              void* d_out, int out_size)
{
    const float* x    = (const float*)d_in[0];
    const float* Wq   = (const float*)d_in[1];
    const float* Wk   = (const float*)d_in[2];
    const float* Wv   = (const float*)d_in[3];
    const float* Wout = (const float*)d_in[4];
    float* out = (float*)d_out;

    cudaFuncSetAttribute(attn_chunk,
                         cudaFuncAttributeMaxDynamicSharedMemorySize,
                         SMEM_B_BYTES);
    cudaFuncSetAttribute(gemm_qkv_tc,
                         cudaFuncAttributeMaxDynamicSharedMemorySize,
                         SMEM_GEMM_BYTES);
    cudaFuncSetAttribute(gemm_out_tc,
                         cudaFuncAttributeMaxDynamicSharedMemorySize,
                         SMEM_GEMM_BYTES);

    split_x <<<BT * DM / 1024, 256>>>(x);                        // idx 0
    split_w4<<<dim3(DM * DM / 1024, 4), 256>>>(Wq, Wk, Wv, Wout); // idx 1
    nop_k   <<<1, 32>>>();                                        // idx 2
    gemm_qkv_tc <<<dim3(BT / 128, 12), 256, SMEM_GEMM_BYTES>>>(); // idx 3 (profiled)
    chunk_kv     <<<dim3(NCHUNK, NBH), 256>>>();
    prefix_state2<<<dim3(16, NBH), 256>>>();
    attn_chunk   <<<dim3(NCHUNK, NBH), 256, SMEM_B_BYTES>>>();
    gemm_out_tc  <<<dim3(BT / 128, 4), 256, SMEM_GEMM_BYTES>>>(out);
}